// round 15
// baseline (speedup 1.0000x reference)
#include <cuda_runtime.h>
#include <cuda_bf16.h>
#include <math.h>

// x [B=8, C=3, T=512, H=64, W=64] fp32 -> out [8, 512] fp32
// out[b] = Vt[1] * explained_variance[1] of PCA.fit(spatial_mean(x[b])).
// Closed-form eigen replaces SVD (see prior rounds).
//
// PERSISTENT one-wave variant: 1184 blocks (148 SM x occ 8) grid-stride
// over 12288 rows (10-11 rows each). Per-row body identical to the best
// measured kernel. Eliminates ~10 wave transitions + 11k block setups.
// Per-batch completion counters; finisher(s) run after a block's loop.

#define B 8
#define C 3
#define T 512
#define HW 4096
#define NROWS (B * C * T)                 // 12288
#define BLOCKS_PER_BATCH (NROWS / B)      // 1536 rows per batch
#define GRID 1184                         // 148 * 8, one full wave

__device__ float g_xm[NROWS];             // spatial means, [B][C][T]
__device__ unsigned int g_count[B];       // zero-init; finisher-reset

__device__ __forceinline__ void run_finisher(int b, int tid, int warp, int lane,
                                             float* __restrict__ out) {
    const float* __restrict__ X = g_xm + b * (C * T);
    const int t0 = tid;            // 0..255
    const int t1 = tid + 256;      // 256..511

    float a0 = __ldcg(&X[t0]), a1 = __ldcg(&X[T + t0]), a2 = __ldcg(&X[2 * T + t0]);
    float b0 = __ldcg(&X[t1]), b1 = __ldcg(&X[T + t1]), b2 = __ldcg(&X[2 * T + t1]);
    float ma = (a0 + a1 + a2) * (1.0f / 3.0f);
    float mb = (b0 + b1 + b2) * (1.0f / 3.0f);
    const float ca0 = a0 - ma, ca1 = a1 - ma, ca2 = a2 - ma;
    const float cb0 = b0 - mb, cb1 = b1 - mb, cb2 = b2 - mb;

    float g[6];
    g[0] = ca0 * ca0 + cb0 * cb0;
    g[1] = ca0 * ca1 + cb0 * cb1;
    g[2] = ca0 * ca2 + cb0 * cb2;
    g[3] = ca1 * ca1 + cb1 * cb1;
    g[4] = ca1 * ca2 + cb1 * cb2;
    g[5] = ca2 * ca2 + cb2 * cb2;

#pragma unroll
    for (int k = 0; k < 6; k++) {
#pragma unroll
        for (int o = 16; o > 0; o >>= 1)
            g[k] += __shfl_xor_sync(0xffffffffu, g[k], o);
    }

    __shared__ float red[8][8];
    if (lane == 0) {
#pragma unroll
        for (int k = 0; k < 6; k++) red[warp][k] = g[k];
    }
    __syncthreads();

    __shared__ float sh_u[3];
    __shared__ float sh_scale;

    if (warp == 0) {
        float G[6];
#pragma unroll
        for (int k = 0; k < 6; k++) {
            float v = (lane < 8) ? red[lane][k] : 0.0f;
#pragma unroll
            for (int o = 4; o > 0; o >>= 1)
                v += __shfl_xor_sync(0xffffffffu, v, o);
            G[k] = v;
        }
        if (lane == 0) {
            const float G00 = G[0], G01 = G[1], G02 = G[2];
            const float G11 = G[3], G12 = G[4], G22 = G[5];
            const float a = 0.70710678f;    // 1/sqrt(2)
            const float d = 0.40824829f;    // 1/sqrt(6)
            const float H11 = a * a * (G00 - 2.0f * G01 + G11);
            const float H12 = a * d * (G00 - G11 - 2.0f * G02 + 2.0f * G12);
            const float H22 = d * d * (G00 + 2.0f * G01 + G11
                                       - 4.0f * G02 - 4.0f * G12 + 4.0f * G22);

            const float mid  = 0.5f * (H11 + H22);
            const float diff = 0.5f * (H11 - H22);
            const float rad  = sqrtf(diff * diff + H12 * H12);
            float lam1 = mid - rad;
            if (lam1 < 0.0f) lam1 = 0.0f;

            float v0a = H12,        v1a = lam1 - H11;
            float v0b = lam1 - H22, v1b = H12;
            float na = v0a * v0a + v1a * v1a;
            float nb = v0b * v0b + v1b * v1b;
            float e0 = (na >= nb) ? v0a : v0b;
            float e1 = (na >= nb) ? v1a : v1b;
            float nn2 = e0 * e0 + e1 * e1;
            if (nn2 < 1e-30f) { e0 = 1.0f; e1 = 0.0f; nn2 = 1.0f; }
            const float rinv = rsqrtf(nn2);
            e0 *= rinv; e1 *= rinv;

            float u0  = a * e0 + d * e1;
            float u1v = -a * e0 + d * e1;
            float u2  = -2.0f * d * e1;

            float au0 = fabsf(u0), au1 = fabsf(u1v), au2 = fabsf(u2);
            float pick = u0, best = au0;
            if (au1 > best) { best = au1; pick = u1v; }
            if (au2 > best) { best = au2; pick = u2; }
            const float sgn = (pick < 0.0f) ? -1.0f : 1.0f;

            sh_u[0] = u0; sh_u[1] = u1v; sh_u[2] = u2;
            sh_scale = sgn * 0.5f * sqrtf(lam1);
        }
    }
    __syncthreads();

    const float sc = sh_scale;
    const float u0 = sh_u[0], u1 = sh_u[1], u2 = sh_u[2];
    out[b * T + t0] = sc * (ca0 * u0 + ca1 * u1 + ca2 * u2);
    out[b * T + t1] = sc * (cb0 * u0 + cb1 * u1 + cb2 * u2);
    __syncthreads();   // red[][] reuse safety across finisher iterations
}

__global__ void __launch_bounds__(256) fused_pca_kernel(
        const float* __restrict__ x, float* __restrict__ out) {
    const int tid  = threadIdx.x;
    const int warp = tid >> 5;
    const int lane = tid & 31;

    __shared__ unsigned int sh_mask;
    if (tid == 0) sh_mask = 0u;
    __syncthreads();

    // ---- phase 1: persistent grid-stride over rows ----
    for (int row = blockIdx.x; row < NROWS; row += GRID) {
        const float4* __restrict__ p =
            reinterpret_cast<const float4*>(x + (size_t)row * HW);

        float4 v0 = __ldg(&p[tid]);
        float4 v1 = __ldg(&p[tid + 256]);
        float4 v2 = __ldg(&p[tid + 512]);
        float4 v3 = __ldg(&p[tid + 768]);

        float s0 = (v0.x + v0.y) + (v0.z + v0.w);
        float s1 = (v1.x + v1.y) + (v1.z + v1.w);
        float s2 = (v2.x + v2.y) + (v2.z + v2.w);
        float s3 = (v3.x + v3.y) + (v3.z + v3.w);
        float s = (s0 + s1) + (s2 + s3);

#pragma unroll
        for (int o = 16; o > 0; o >>= 1) s += __shfl_xor_sync(0xffffffffu, s, o);

        __shared__ float ws[8];
        if (lane == 0) ws[warp] = s;
        __syncthreads();

        if (tid == 0) {
            float v = ws[0];
#pragma unroll
            for (int k = 1; k < 8; k++) v += ws[k];
            g_xm[row] = v * (1.0f / (float)HW);
            __threadfence();                    // publish before counting
            const int b = row / BLOCKS_PER_BATCH;
            unsigned int c = atomicAdd(&g_count[b], 1u);
            if (c == BLOCKS_PER_BATCH - 1u) sh_mask |= (1u << b);
        }
        __syncthreads();        // ws reuse + sh_mask visibility
    }

    // ---- phase 2: run finishers for any batches this block completed ----
    unsigned int mask = sh_mask;
    while (mask) {
        const int b = __ffs(mask) - 1;
        mask &= mask - 1;
        if (tid == 0) g_count[b] = 0u;   // reset for next graph replay
        run_finisher(b, tid, warp, lane, out);
    }
}

extern "C" void kernel_launch(void* const* d_in, const int* in_sizes, int n_in,
                              void* d_out, int out_size) {
    const float* x = (const float*)d_in[0];
    float* out = (float*)d_out;
    (void)in_sizes; (void)n_in; (void)out_size;

    fused_pca_kernel<<<GRID, 256>>>(x, out);
}

// round 16
// speedup vs baseline: 1.1223x; 1.1223x over previous
#include <cuda_runtime.h>
#include <cuda_bf16.h>
#include <math.h>

// x [B=8, C=3, T=512, H=64, W=64] fp32 -> out [8, 512] fp32
// out[b] = Vt[1] * explained_variance[1] of PCA.fit(spatial_mean(x[b])).
// Closed-form: centering over C=3 => (1,1,1)/sqrt3 null vector of G=Xc Xc^T;
// 2x2 projected eigenproblem; out = sgn*sqrt(lam1)/2 * Xc^T u1.
//
// FINAL (best measured 35.33us = 201.3MB / ~5.7TB/s platform stream ceiling,
// confirmed across 8 structural variants): fused single launch, block-per-row
// streaming (4 upfront float4/thread), flat per-batch completion counter
// + threadfence, per-batch finisher block.

#define B 8
#define C 3
#define T 512
#define HW 4096
#define NROWS (B * C * T)                 // 12288
#define BLOCKS_PER_BATCH (NROWS / B)      // 1536

__device__ float g_xm[NROWS];             // spatial means, [B][C][T]
__device__ unsigned int g_count[B];       // zero-init; self-resetting

__global__ void __launch_bounds__(256) fused_pca_kernel(
        const float* __restrict__ x, float* __restrict__ out) {
    const int row  = blockIdx.x;                       // one row per block
    const int tid  = threadIdx.x;
    const int warp = tid >> 5;
    const int lane = tid & 31;

    // ---- phase 1: streaming mean over 4096 floats (HBM-bound) ----
    const float4* __restrict__ p =
        reinterpret_cast<const float4*>(x + (size_t)row * HW);

    float4 v0 = __ldg(&p[tid]);
    float4 v1 = __ldg(&p[tid + 256]);
    float4 v2 = __ldg(&p[tid + 512]);
    float4 v3 = __ldg(&p[tid + 768]);

    float s0 = (v0.x + v0.y) + (v0.z + v0.w);
    float s1 = (v1.x + v1.y) + (v1.z + v1.w);
    float s2 = (v2.x + v2.y) + (v2.z + v2.w);
    float s3 = (v3.x + v3.y) + (v3.z + v3.w);
    float s = (s0 + s1) + (s2 + s3);

#pragma unroll
    for (int o = 16; o > 0; o >>= 1) s += __shfl_xor_sync(0xffffffffu, s, o);

    __shared__ float ws[8];
    if (lane == 0) ws[warp] = s;
    __syncthreads();

    const int b = row / BLOCKS_PER_BATCH;   // batch index
    __shared__ unsigned int sh_last;
    if (tid == 0) {
        sh_last = 0u;
        float v = ws[0];
#pragma unroll
        for (int k = 1; k < 8; k++) v += ws[k];
        g_xm[row] = v * (1.0f / (float)HW);
        __threadfence();                    // publish before counting
        unsigned int c = atomicAdd(&g_count[b], 1u);
        if (c == BLOCKS_PER_BATCH - 1u) sh_last = 1u;
    }
    __syncthreads();
    if (!sh_last) return;

    // ---- phase 2: finisher for batch b (one block; L2-hot 6KB) ----
    if (tid == 0) g_count[b] = 0u;          // reset for next graph replay

    const float* __restrict__ X = g_xm + b * (C * T);
    const int t0 = tid;            // 0..255
    const int t1 = tid + 256;      // 256..511

    float a0 = __ldcg(&X[t0]), a1 = __ldcg(&X[T + t0]), a2 = __ldcg(&X[2 * T + t0]);
    float b0 = __ldcg(&X[t1]), b1 = __ldcg(&X[T + t1]), b2 = __ldcg(&X[2 * T + t1]);
    float ma = (a0 + a1 + a2) * (1.0f / 3.0f);
    float mb = (b0 + b1 + b2) * (1.0f / 3.0f);
    const float ca0 = a0 - ma, ca1 = a1 - ma, ca2 = a2 - ma;
    const float cb0 = b0 - mb, cb1 = b1 - mb, cb2 = b2 - mb;

    float g[6];
    g[0] = ca0 * ca0 + cb0 * cb0;   // G00
    g[1] = ca0 * ca1 + cb0 * cb1;   // G01
    g[2] = ca0 * ca2 + cb0 * cb2;   // G02
    g[3] = ca1 * ca1 + cb1 * cb1;   // G11
    g[4] = ca1 * ca2 + cb1 * cb2;   // G12
    g[5] = ca2 * ca2 + cb2 * cb2;   // G22

#pragma unroll
    for (int k = 0; k < 6; k++) {
#pragma unroll
        for (int o = 16; o > 0; o >>= 1)
            g[k] += __shfl_xor_sync(0xffffffffu, g[k], o);
    }

    __shared__ float red[8][8];     // 8 warps x 6 entries (padded)
    if (lane == 0) {
#pragma unroll
        for (int k = 0; k < 6; k++) red[warp][k] = g[k];
    }
    __syncthreads();

    __shared__ float sh_u[3];
    __shared__ float sh_scale;

    if (warp == 0) {
        float G[6];
#pragma unroll
        for (int k = 0; k < 6; k++) {
            float v = (lane < 8) ? red[lane][k] : 0.0f;
#pragma unroll
            for (int o = 4; o > 0; o >>= 1)
                v += __shfl_xor_sync(0xffffffffu, v, o);
            G[k] = v;
        }
        if (lane == 0) {
            const float G00 = G[0], G01 = G[1], G02 = G[2];
            const float G11 = G[3], G12 = G[4], G22 = G[5];
            // orthonormal basis _|_ (1,1,1): a*(1,-1,0), d*(1,1,-2)
            const float a = 0.70710678f;    // 1/sqrt(2)
            const float d = 0.40824829f;    // 1/sqrt(6)
            const float H11 = a * a * (G00 - 2.0f * G01 + G11);
            const float H12 = a * d * (G00 - G11 - 2.0f * G02 + 2.0f * G12);
            const float H22 = d * d * (G00 + 2.0f * G01 + G11
                                       - 4.0f * G02 - 4.0f * G12 + 4.0f * G22);

            const float mid  = 0.5f * (H11 + H22);
            const float diff = 0.5f * (H11 - H22);
            const float rad  = sqrtf(diff * diff + H12 * H12);
            float lam1 = mid - rad;         // second-largest eig of G
            if (lam1 < 0.0f) lam1 = 0.0f;

            float v0a = H12,        v1a = lam1 - H11;
            float v0b = lam1 - H22, v1b = H12;
            float na = v0a * v0a + v1a * v1a;
            float nb = v0b * v0b + v1b * v1b;
            float e0 = (na >= nb) ? v0a : v0b;
            float e1 = (na >= nb) ? v1a : v1b;
            float nn2 = e0 * e0 + e1 * e1;
            if (nn2 < 1e-30f) { e0 = 1.0f; e1 = 0.0f; nn2 = 1.0f; }
            const float rinv = rsqrtf(nn2);
            e0 *= rinv; e1 *= rinv;

            float u0  = a * e0 + d * e1;
            float u1v = -a * e0 + d * e1;
            float u2  = -2.0f * d * e1;

            // svd_flip: sign of max-|.| component (first occurrence)
            float au0 = fabsf(u0), au1 = fabsf(u1v), au2 = fabsf(u2);
            float pick = u0, best = au0;
            if (au1 > best) { best = au1; pick = u1v; }
            if (au2 > best) { best = au2; pick = u2; }
            const float sgn = (pick < 0.0f) ? -1.0f : 1.0f;

            sh_u[0] = u0; sh_u[1] = u1v; sh_u[2] = u2;
            sh_scale = sgn * 0.5f * sqrtf(lam1);
        }
    }
    __syncthreads();

    const float sc = sh_scale;
    const float u0 = sh_u[0], u1 = sh_u[1], u2 = sh_u[2];
    out[b * T + t0] = sc * (ca0 * u0 + ca1 * u1 + ca2 * u2);
    out[b * T + t1] = sc * (cb0 * u0 + cb1 * u1 + cb2 * u2);
}

extern "C" void kernel_launch(void* const* d_in, const int* in_sizes, int n_in,
                              void* d_out, int out_size) {
    const float* x = (const float*)d_in[0];
    float* out = (float*)d_out;
    (void)in_sizes; (void)n_in; (void)out_size;

    fused_pca_kernel<<<NROWS, 256>>>(x, out);
}